// round 1
// baseline (speedup 1.0000x reference)
#include <cuda_runtime.h>

// Shapes (fixed for this problem instance):
// x: (4,128,256,256) fp32; conv1_w (256,128); conv2_w (256,128); hop=128, pad=64
// out: (4,2,256,32768) fp32

__device__ float g_xP[4ull * 256 * 128 * 256];   // prelu(x) transposed to [b][s][d][k]
__device__ float g_W1t[128 * 256];               // W1 transposed: [d][o]
__device__ float g_W2t[128 * 256];               // W2 transposed: [e][o]

// ---------------------------------------------------------------------------
// Weight transpose: W1t[d][o] = w1[o][d], W2t[e][o] = w2[o][e]
// ---------------------------------------------------------------------------
__global__ void prep_w_kernel(const float* __restrict__ w1,
                              const float* __restrict__ w2) {
    int tid = blockIdx.x * 256 + threadIdx.x;     // 65536 threads total
    int o = tid & 255;
    int d = (tid >> 8) & 127;
    if (tid < 32768) g_W1t[d * 256 + o] = w1[o * 128 + d];
    else             g_W2t[d * 256 + o] = w2[o * 128 + d];
}

// ---------------------------------------------------------------------------
// x prep: prelu + transpose (b,d,k,s) -> (b,s,d,k), 32x32 smem tiles
// ---------------------------------------------------------------------------
__global__ void prep_x_kernel(const float* __restrict__ x,
                              const float* __restrict__ pw_ptr) {
    __shared__ float tile[32][33];
    int bd = blockIdx.z;          // b*128 + d
    int d  = bd & 127;
    int b  = bd >> 7;
    int k0 = blockIdx.y * 32, s0 = blockIdx.x * 32;
    float pw = *pw_ptr;
    const float* src = x + (size_t)bd * 65536;    // x[b,d,:,:]
#pragma unroll
    for (int i = 0; i < 4; i++) {
        int k = k0 + threadIdx.y + i * 8;
        float v = src[k * 256 + s0 + threadIdx.x];            // coalesced along s
        tile[threadIdx.y + i * 8][threadIdx.x] = (v >= 0.f) ? v : pw * v;
    }
    __syncthreads();
    float* dst = g_xP + (size_t)b * (256 * 128 * 256);
#pragma unroll
    for (int i = 0; i < 4; i++) {
        int s = s0 + threadIdx.y + i * 8;
        dst[(s * 128 + d) * 256 + k0 + threadIdx.x] =          // coalesced along k
            tile[threadIdx.x][threadIdx.y + i * 8];
    }
}

// ---------------------------------------------------------------------------
// Block GEMM: acc[8][8] += Wg(128x256, k-major)^T-style @ A(128x128 in smem)
// Thread map: tx = tid&15 -> 8 cols (p), ty = tid>>4 -> 8 rows (o). 512 threads.
// Weight chunks (8 k x 256) streamed gmem->smem with register prefetch.
// ---------------------------------------------------------------------------
__device__ __forceinline__ void run_gemm(const float* __restrict__ Wg,
                                         const float* A_, float* Wc,
                                         int tx, int ty, int tid,
                                         float acc[8][8]) {
    float4 nxt = *(const float4*)(Wg + tid * 4);
    for (int ch = 0; ch < 16; ++ch) {
        __syncthreads();                       // Wc free + prior-phase smem visible
        *(float4*)(Wc + tid * 4) = nxt;
        __syncthreads();
        if (ch < 15) nxt = *(const float4*)(Wg + (ch + 1) * 2048 + tid * 4);
#pragma unroll
        for (int kk = 0; kk < 8; ++kk) {
            const float* arow = A_ + (ch * 8 + kk) * 132 + tx * 8;
            const float* wrow = Wc + kk * 256 + ty * 8;
            float4 a0 = *(const float4*)arow;
            float4 a1 = *(const float4*)(arow + 4);
            float4 w0 = *(const float4*)wrow;
            float4 w1v = *(const float4*)(wrow + 4);
            float a[8] = {a0.x, a0.y, a0.z, a0.w, a1.x, a1.y, a1.z, a1.w};
            float w[8] = {w0.x, w0.y, w0.z, w0.w, w1v.x, w1v.y, w1v.z, w1v.w};
#pragma unroll
            for (int m = 0; m < 8; m++)
#pragma unroll
                for (int n = 0; n < 8; n++)
                    acc[m][n] = fmaf(w[m], a[n], acc[m][n]);
        }
    }
}

// ---------------------------------------------------------------------------
// Fused main kernel: one CTA per (time-tile j, batch b).
//   t in [128j, 128j+128), output l = t - 64 (valid iff 0 <= l < 32768)
//   A_sum = xP[b][j][:, 0:128] + xP[b][j-1][:, 128:256]   (pre-OLA summation)
//   Z = W1 @ A_sum + nf*b1 ; relu ; Out_c = W2 @ Z_c + b2
// ---------------------------------------------------------------------------
__global__ __launch_bounds__(512, 1) void main_kernel(
    const float* __restrict__ b1, const float* __restrict__ b2,
    float* __restrict__ out) {
    extern __shared__ float sm[];
    float* As = sm;                         // 128 x 132
    float* Zs = sm + 128 * 132;             // 256 x 132
    float* Wc = Zs + 256 * 132;             // 8 x 256 chunk
    int j = blockIdx.x;                     // 0..256
    int b = blockIdx.y;                     // 0..3
    int tid = threadIdx.x;
    int tx = tid & 15, ty = tid >> 4;

    // ---- Load + OLA-presum A tile (coalesced float4) ----
    {
        const float4* xPb = (const float4*)g_xP + (size_t)b * (256 * 128 * 64);
        for (int i = tid; i < 128 * 32; i += 512) {
            int d = i >> 5, p4 = i & 31;
            float4 v = make_float4(0.f, 0.f, 0.f, 0.f);
            if (j < 256) v = xPb[(j * 128 + d) * 64 + p4];
            if (j > 0) {
                float4 t = xPb[((j - 1) * 128 + d) * 64 + 32 + p4];
                v.x += t.x; v.y += t.y; v.z += t.z; v.w += t.w;
            }
            *(float4*)(As + d * 132 + p4 * 4) = v;
        }
    }
    float nf = (j == 0 || j == 256) ? 1.f : 2.f;   // frames contributing (bias count)

    float acc[8][8];
#pragma unroll
    for (int m = 0; m < 8; m++)
#pragma unroll
        for (int n = 0; n < 8; n++) acc[m][n] = 0.f;

    // ---- GEMM1: Z = W1 @ A_sum ----
    run_gemm(g_W1t, As, Wc, tx, ty, tid, acc);

    // ---- bias + relu -> Zs ----
    int orow = ty * 8;
#pragma unroll
    for (int m = 0; m < 8; m++) {
        float bo = nf * __ldg(b1 + orow + m);
        float4 z0, z1;
        z0.x = fmaxf(acc[m][0] + bo, 0.f);
        z0.y = fmaxf(acc[m][1] + bo, 0.f);
        z0.z = fmaxf(acc[m][2] + bo, 0.f);
        z0.w = fmaxf(acc[m][3] + bo, 0.f);
        z1.x = fmaxf(acc[m][4] + bo, 0.f);
        z1.y = fmaxf(acc[m][5] + bo, 0.f);
        z1.z = fmaxf(acc[m][6] + bo, 0.f);
        z1.w = fmaxf(acc[m][7] + bo, 0.f);
        float* zr = Zs + (orow + m) * 132 + tx * 8;
        *(float4*)zr = z0;
        *(float4*)(zr + 4) = z1;
    }
    // (Zs-write -> Zs-read hazard covered by the double sync at the top of run_gemm)

    // ---- GEMM2 per c: Out_c = W2 @ relu(Z_c) + b2, store with l = t-64 shift ----
    int l0 = j * 128 - 64 + tx * 8;
    bool valid = (j > 0 || tx >= 8) && (j < 256 || tx < 8);   // exactly 0<=l<32768

    for (int c = 0; c < 2; c++) {
#pragma unroll
        for (int m = 0; m < 8; m++)
#pragma unroll
            for (int n = 0; n < 8; n++) acc[m][n] = 0.f;

        run_gemm(g_W2t, Zs + c * (128 * 132), Wc, tx, ty, tid, acc);

        if (valid) {
#pragma unroll
            for (int m = 0; m < 8; m++) {
                float bo = __ldg(b2 + orow + m);
                float4 r0, r1;
                r0.x = acc[m][0] + bo; r0.y = acc[m][1] + bo;
                r0.z = acc[m][2] + bo; r0.w = acc[m][3] + bo;
                r1.x = acc[m][4] + bo; r1.y = acc[m][5] + bo;
                r1.z = acc[m][6] + bo; r1.w = acc[m][7] + bo;
                float* dst = out +
                    (size_t)((b * 2 + c) * 256 + orow + m) * 32768 + l0;
                *(float4*)dst = r0;
                *(float4*)(dst + 4) = r1;
            }
        }
    }
}

// ---------------------------------------------------------------------------
extern "C" void kernel_launch(void* const* d_in, const int* in_sizes, int n_in,
                              void* d_out, int out_size) {
    const float* x  = (const float*)d_in[0];
    const float* pw = (const float*)d_in[1];
    const float* w1 = (const float*)d_in[2];
    const float* b1 = (const float*)d_in[3];
    const float* w2 = (const float*)d_in[4];
    const float* b2 = (const float*)d_in[5];
    float* out = (float*)d_out;

    const int smem = (128 * 132 + 256 * 132 + 8 * 256) * 4;   // 210944 B
    cudaFuncSetAttribute(main_kernel,
                         cudaFuncAttributeMaxDynamicSharedMemorySize, smem);

    prep_w_kernel<<<256, 256>>>(w1, w2);
    prep_x_kernel<<<dim3(8, 8, 512), dim3(32, 8)>>>(x, pw);
    main_kernel<<<dim3(257, 4), 512, smem>>>(b1, b2, out);
}

// round 3
// speedup vs baseline: 2.2731x; 2.2731x over previous
#include <cuda_runtime.h>
#include <cuda_bf16.h>
#include <cstdint>

#define NB 4
#define ND 128
#define NK 256
#define NS 256
#define NJ 257
#define NO 256
#define TOUT 32768

// ---------------- scratch ----------------
__device__ float g_xP[(size_t)NB*NS*NK*ND];                 // prelu(x) as [b][s][k][d]
__device__ __nv_bfloat16 g_W1h[NO*ND], g_W1l[NO*ND];
__device__ __nv_bfloat16 g_W2h[NO*ND], g_W2l[NO*ND];

// smem map (bytes)
#define SM_B1 0
#define SM_B2 1024
#define SM_W  4096                  // 128KB: W1h|W1l ; later Zh(c0,c1)|Zl(c0,c1)
#define SM_A  (SM_W + 131072)       // 64KB: Ah|Al ; later W2half h|l
#define SM_TOT (SM_A + 65536)       // 200704

__device__ __forceinline__ uint32_t smem_u32(const void* p) {
    uint32_t a;
    asm("{ .reg .u64 t; cvta.to.shared.u64 t, %1; cvt.u32.u64 %0, t; }" : "=r"(a) : "l"(p));
    return a;
}
// rows of 256B; 16B-chunk XOR swizzle -> conflict-free ldmatrix
__device__ __forceinline__ uint32_t swz(uint32_t row, uint32_t byteCol) {
    return row * 256u + ((((byteCol >> 4) ^ (row & 7)) << 4) | (byteCol & 15));
}
#define LDSM4(r0,r1,r2,r3,addr) \
    asm volatile("ldmatrix.sync.aligned.m8n8.x4.shared.b16 {%0,%1,%2,%3}, [%4];" \
        : "=r"(r0),"=r"(r1),"=r"(r2),"=r"(r3) : "r"(addr))

__device__ __forceinline__ void mma16816(float d[4], const uint32_t a[4], uint32_t b0, uint32_t b1) {
    asm volatile("mma.sync.aligned.m16n8k16.row.col.f32.bf16.bf16.f32 "
        "{%0,%1,%2,%3}, {%4,%5,%6,%7}, {%8,%9}, {%0,%1,%2,%3};"
        : "+f"(d[0]), "+f"(d[1]), "+f"(d[2]), "+f"(d[3])
        : "r"(a[0]), "r"(a[1]), "r"(a[2]), "r"(a[3]), "r"(b0), "r"(b1));
}
__device__ __forceinline__ void split2(float a, float b, uint32_t& h, uint32_t& l) {
    __nv_bfloat16 ha = __float2bfloat16_rn(a), hb = __float2bfloat16_rn(b);
    __nv_bfloat162 hv; hv.x = ha; hv.y = hb;
    __nv_bfloat162 lv;
    lv.x = __float2bfloat16_rn(a - __bfloat162float(ha));
    lv.y = __float2bfloat16_rn(b - __bfloat162float(hb));
    h = *(uint32_t*)&hv; l = *(uint32_t*)&lv;
}

// 3-term split GEMM tile: acc[4][2*NG] m16n8 tiles; A-op rows p (m), B-op rows o (n), K=128.
template<int NG>
__device__ __forceinline__ void gemm_tile(uint32_t aH, uint32_t aL, uint32_t wH, uint32_t wL,
                                          float acc[4][2*NG][4], int lane, int pw, int ow)
{
    int ar = pw + (lane & 15);
    uint32_t acb = (uint32_t)(lane >> 4) << 4;
    int br = ow + ((lane >> 3) & 1) * 8 + (lane & 7);
    uint32_t bcb = (uint32_t)((lane >> 4) & 1) << 4;
#pragma unroll
    for (int t = 0; t < 3; t++) {
        uint32_t ab = (t == 1) ? aL : aH;
        uint32_t wb = (t == 2) ? wL : wH;
#pragma unroll
        for (int ks = 0; ks < 8; ks++) {
            uint32_t kb = (uint32_t)ks * 32;
            uint32_t a[4][4];
#pragma unroll
            for (int mt = 0; mt < 4; mt++)
                LDSM4(a[mt][0], a[mt][1], a[mt][2], a[mt][3], ab + swz(ar + mt * 16, kb + acb));
            uint32_t bf[NG][4];
#pragma unroll
            for (int ng = 0; ng < NG; ng++)
                LDSM4(bf[ng][0], bf[ng][1], bf[ng][2], bf[ng][3], wb + swz(br + ng * 16, kb + bcb));
#pragma unroll
            for (int mt = 0; mt < 4; mt++)
#pragma unroll
                for (int ng = 0; ng < NG; ng++) {
                    mma16816(acc[mt][2 * ng],     a[mt], bf[ng][0], bf[ng][2]);
                    mma16816(acc[mt][2 * ng + 1], a[mt], bf[ng][1], bf[ng][3]);
                }
        }
    }
}

// ---------------- prep kernels ----------------
__global__ void prep_w(const float* __restrict__ w1, const float* __restrict__ w2) {
    int i = blockIdx.x * 256 + threadIdx.x;
    if (i < NO * ND) {
        float v = w1[i];
        __nv_bfloat16 h = __float2bfloat16_rn(v);
        g_W1h[i] = h; g_W1l[i] = __float2bfloat16_rn(v - __bfloat162float(h));
    } else {
        int k = i - NO * ND;
        float v = w2[k];
        __nv_bfloat16 h = __float2bfloat16_rn(v);
        g_W2h[k] = h; g_W2l[k] = __float2bfloat16_rn(v - __bfloat162float(h));
    }
}

// prelu + transpose (b,d,k,s) -> (b,s,k,d)
__global__ void prep_x(const float* __restrict__ x, const float* __restrict__ pw_ptr) {
    __shared__ float t[32][33];
    int bk = blockIdx.z;
    int k = bk & 255, b = bk >> 8;
    int d0 = blockIdx.y * 32, s0 = blockIdx.x * 32;
    float pw = *pw_ptr;
#pragma unroll
    for (int i = 0; i < 4; i++) {
        int d = d0 + threadIdx.y + i * 8;
        float v = x[(((size_t)b * ND + d) * NK + k) * NS + s0 + threadIdx.x];
        t[threadIdx.y + i * 8][threadIdx.x] = (v >= 0.f) ? v : pw * v;
    }
    __syncthreads();
#pragma unroll
    for (int i = 0; i < 4; i++) {
        int s = s0 + threadIdx.y + i * 8;
        g_xP[(((size_t)b * NS + s) * NK + k) * ND + d0 + threadIdx.x] = t[threadIdx.x][threadIdx.y + i * 8];
    }
}

// ---------------- fused main kernel ----------------
__global__ __launch_bounds__(256, 1) void main_kernel(
    const float* __restrict__ b1g, const float* __restrict__ b2g, float* __restrict__ out)
{
    extern __shared__ char smc[];
    uint32_t sb = smem_u32(smc);
    float* s_b1 = (float*)(smc + SM_B1);
    float* s_b2 = (float*)(smc + SM_B2);
    int tid = threadIdx.x, w = tid >> 5, lane = tid & 31;
    int j = blockIdx.x, b = blockIdx.y;
    int pw = (w & 1) * 64, ow = (w >> 1) * 64;

    s_b1[tid] = b1g[tid];
    s_b2[tid] = b2g[tid];

    // ---- W1 full h/l -> SM_W ----
    {
        const uint4* h4 = (const uint4*)g_W1h;
        const uint4* l4 = (const uint4*)g_W1l;
        for (int idx = tid; idx < 4096; idx += 256) {
            uint32_t off = swz(idx >> 4, (idx & 15) << 4);
            *(uint4*)(smc + SM_W + off) = h4[idx];
            *(uint4*)(smc + SM_W + 65536 + off) = l4[idx];
        }
    }
    // ---- A tile: OLA pre-sum of two frame halves, bf16 h/l split -> SM_A ----
    {
        const float* x1 = g_xP + ((size_t)b * NS + j) * (NK * ND);         // s=j,   k=row
        const float* x2 = g_xP + ((size_t)b * NS + (j - 1)) * (NK * ND);   // s=j-1, k=row+128
        for (int idx = tid; idx < 2048; idx += 256) {
            int row = idx >> 4, ch = idx & 15;
            float v[8];
#pragma unroll
            for (int q = 0; q < 8; q++) v[q] = 0.f;
            if (j < 256) {
                const float4* p4 = (const float4*)(x1 + row * ND + ch * 8);
                float4 u0 = p4[0], u1 = p4[1];
                v[0] = u0.x; v[1] = u0.y; v[2] = u0.z; v[3] = u0.w;
                v[4] = u1.x; v[5] = u1.y; v[6] = u1.z; v[7] = u1.w;
            }
            if (j > 0) {
                const float4* p4 = (const float4*)(x2 + (row + 128) * ND + ch * 8);
                float4 u0 = p4[0], u1 = p4[1];
                v[0] += u0.x; v[1] += u0.y; v[2] += u0.z; v[3] += u0.w;
                v[4] += u1.x; v[5] += u1.y; v[6] += u1.z; v[7] += u1.w;
            }
            uint32_t hw[4], lw[4];
#pragma unroll
            for (int q = 0; q < 4; q++) split2(v[2 * q], v[2 * q + 1], hw[q], lw[q]);
            uint32_t off = swz(row, (uint32_t)ch << 4);
            *(uint4*)(smc + SM_A + off) = make_uint4(hw[0], hw[1], hw[2], hw[3]);
            *(uint4*)(smc + SM_A + 32768 + off) = make_uint4(lw[0], lw[1], lw[2], lw[3]);
        }
    }
    __syncthreads();

    // ---- GEMM1: D1[p=128][o=256] = A[p][d] * W1[o][d] ----
    float acc1[4][8][4];
#pragma unroll
    for (int mt = 0; mt < 4; mt++)
#pragma unroll
        for (int nt = 0; nt < 8; nt++)
#pragma unroll
            for (int q = 0; q < 4; q++) acc1[mt][nt][q] = 0.f;

    gemm_tile<4>(sb + SM_A, sb + SM_A + 32768, sb + SM_W, sb + SM_W + 65536, acc1, lane, pw, ow);
    __syncthreads();   // all SM_W / SM_A reads done

    // ---- epilogue1: Z = relu(D1 + nf*b1) -> bf16 h/l into SM_W region ----
    float nf = (j == 0 || j == 256) ? 1.f : 2.f;
    int lr = lane >> 2, lc = (lane & 3) << 1;
    int cW = ow >> 7;                          // this warp's channel
    char* zhB = smc + SM_W + cW * 32768;
    char* zlB = smc + SM_W + 65536 + cW * 32768;
#pragma unroll
    for (int mt = 0; mt < 4; mt++) {
#pragma unroll
        for (int nt = 0; nt < 8; nt++) {
            int o = ow + nt * 8 + lc;
            int e = o & 127;
            float b0v = nf * s_b1[o], b1v = nf * s_b1[o + 1];
#pragma unroll
            for (int hf = 0; hf < 2; hf++) {
                int p = pw + mt * 16 + lr + hf * 8;
                float z0 = fmaxf(acc1[mt][nt][hf * 2]     + b0v, 0.f);
                float z1 = fmaxf(acc1[mt][nt][hf * 2 + 1] + b1v, 0.f);
                uint32_t h, l;
                split2(z0, z1, h, l);
                uint32_t off = swz((uint32_t)p, (uint32_t)e << 1);
                *(uint32_t*)(zhB + off) = h;
                *(uint32_t*)(zlB + off) = l;
            }
        }
    }
    // ---- W2 half 0 (o2 rows 0..127) h/l -> SM_A ----
    {
        const uint4* h4 = (const uint4*)g_W2h;
        const uint4* l4 = (const uint4*)g_W2l;
        for (int idx = tid; idx < 2048; idx += 256) {
            uint32_t off = swz(idx >> 4, (idx & 15) << 4);
            *(uint4*)(smc + SM_A + off) = h4[idx];
            *(uint4*)(smc + SM_A + 32768 + off) = l4[idx];
        }
    }
    __syncthreads();

    // ---- GEMM2: per o2-half, per channel: D2[p=128][o2=128] = Z_c[p][e] * W2[o2][e] ----
    int pw2 = (w & 1) * 64, ow2 = (w >> 1) * 32;
    int l0 = j * 128 - 64;
#pragma unroll 1
    for (int half = 0; half < 2; half++) {
        if (half == 1) {
            __syncthreads();   // prior W2 reads done
            const uint4* h4 = (const uint4*)g_W2h + 2048;
            const uint4* l4 = (const uint4*)g_W2l + 2048;
            for (int idx = tid; idx < 2048; idx += 256) {
                uint32_t off = swz(idx >> 4, (idx & 15) << 4);
                *(uint4*)(smc + SM_A + off) = h4[idx];
                *(uint4*)(smc + SM_A + 32768 + off) = l4[idx];
            }
            __syncthreads();
        }
#pragma unroll 1
        for (int c = 0; c < 2; c++) {
            float acc2[4][4][4];
#pragma unroll
            for (int mt = 0; mt < 4; mt++)
#pragma unroll
                for (int nt = 0; nt < 4; nt++)
#pragma unroll
                    for (int q = 0; q < 4; q++) acc2[mt][nt][q] = 0.f;

            gemm_tile<2>(sb + SM_W + c * 32768, sb + SM_W + 65536 + c * 32768,
                         sb + SM_A, sb + SM_A + 32768, acc2, lane, pw2, ow2);

            float* ob = out + ((size_t)(b * 2 + c) * NO + half * 128) * TOUT;
#pragma unroll
            for (int mt = 0; mt < 4; mt++) {
#pragma unroll
                for (int hf = 0; hf < 2; hf++) {
                    int p = pw2 + mt * 16 + lr + hf * 8;
                    int l = l0 + p;
                    if (l >= 0 && l < TOUT) {
#pragma unroll
                        for (int nt = 0; nt < 4; nt++) {
                            int o2 = ow2 + nt * 8 + lc;
                            ob[(size_t)o2 * TOUT + l]       = acc2[mt][nt][hf * 2]     + s_b2[half * 128 + o2];
                            ob[(size_t)(o2 + 1) * TOUT + l] = acc2[mt][nt][hf * 2 + 1] + s_b2[half * 128 + o2 + 1];
                        }
                    }
                }
            }
        }
    }
}

// ---------------------------------------------------------------------------
extern "C" void kernel_launch(void* const* d_in, const int* in_sizes, int n_in,
                              void* d_out, int out_size) {
    const float* x  = (const float*)d_in[0];
    const float* pw = (const float*)d_in[1];
    const float* w1 = (const float*)d_in[2];
    const float* b1 = (const float*)d_in[3];
    const float* w2 = (const float*)d_in[4];
    const float* b2 = (const float*)d_in[5];
    float* out = (float*)d_out;

    cudaFuncSetAttribute(main_kernel, cudaFuncAttributeMaxDynamicSharedMemorySize, SM_TOT);

    prep_w<<<256, 256>>>(w1, w2);
    prep_x<<<dim3(8, 4, NB * NK), dim3(32, 8)>>>(x, pw);
    main_kernel<<<dim3(NJ, NB), 256, SM_TOT>>>(b1, b2, out);
}

// round 4
// speedup vs baseline: 5.6519x; 2.4865x over previous
#include <cuda_runtime.h>
#include <cuda_fp16.h>
#include <cstdint>

#define NB 4
#define ND 128
#define NK 256
#define NS 256
#define NJ 257
#define NO 256
#define TOUT 32768

// ---------------- scratch ----------------
__device__ __half g_Af[(size_t)NB*NJ*128*ND];   // presummed OLA frames, fp16 [b][j][p][d]
__device__ __half g_W1f[NO*ND];                 // [o][d] fp16
__device__ __half g_W2f[NO*ND];                 // [o2][e] fp16

// smem map
#define SM_B1 0
#define SM_B2 1024
#define SM_W  2048                    // 64KB: W1 then W2
#define SM_AZ (2048 + 65536)          // 64KB: A (32K) then Z (c0|c1, 32K each)
#define SM_TOT (SM_AZ + 65536)        // 133120 B

__device__ __forceinline__ uint32_t smem_u32(const void* p) {
    uint32_t a;
    asm("{ .reg .u64 t; cvta.to.shared.u64 t, %1; cvt.u32.u64 %0, t; }" : "=r"(a) : "l"(p));
    return a;
}
// 256B rows; 16B-chunk XOR swizzle (conflict-free ldmatrix)
__device__ __forceinline__ uint32_t swz(uint32_t row, uint32_t byteCol) {
    return row * 256u + ((((byteCol >> 4) ^ (row & 7)) << 4) | (byteCol & 15));
}
#define LDSM4(r0,r1,r2,r3,addr) \
    asm volatile("ldmatrix.sync.aligned.m8n8.x4.shared.b16 {%0,%1,%2,%3}, [%4];" \
        : "=r"(r0),"=r"(r1),"=r"(r2),"=r"(r3) : "r"(addr))

__device__ __forceinline__ void mma16816(float d[4], const uint32_t a[4], uint32_t b0, uint32_t b1) {
    asm volatile("mma.sync.aligned.m16n8k16.row.col.f32.f16.f16.f32 "
        "{%0,%1,%2,%3}, {%4,%5,%6,%7}, {%8,%9}, {%0,%1,%2,%3};"
        : "+f"(d[0]), "+f"(d[1]), "+f"(d[2]), "+f"(d[3])
        : "r"(a[0]), "r"(a[1]), "r"(a[2]), "r"(a[3]), "r"(b0), "r"(b1));
}

// ---------------- fused prep: W fp16 convert + OLA-presummed A build ----------------
// grid (9, 4, NB*128 + 1); block (32, 8)
__global__ void prep_all(const float* __restrict__ x, const float* __restrict__ pw_ptr,
                         const float* __restrict__ w1, const float* __restrict__ w2)
{
    int tx = threadIdx.x, ty = threadIdx.y;
    int tid = ty * 32 + tx;
    if (blockIdx.z == NB * 128) {
        // ---- W convert: 36 blocks x 256 threads over 65536 elements ----
        int flat = (blockIdx.x * 4 + blockIdx.y) * 256 + tid;
        for (; flat < 2 * NO * ND; flat += 36 * 256) {
            if (flat < NO * ND) g_W1f[flat] = __float2half_rn(w1[flat]);
            else                g_W2f[flat - NO * ND] = __float2half_rn(w2[flat - NO * ND]);
        }
        return;
    }
    // ---- A build: z = b*128 + p ----
    __shared__ float t[32][33];
    int b = blockIdx.z >> 7, p = blockIdx.z & 127;
    int j0 = blockIdx.x * 32, d0 = blockIdx.y * 32;
    float pw = *pw_ptr;
#pragma unroll
    for (int i = 0; i < 4; i++) {
        int d = d0 + ty + i * 8;
        int jj = j0 + tx;
        float acc = 0.f;
        // frame (k=p, s=jj): valid for jj < 256
        if (jj < 256) {
            float v = x[(((size_t)b * ND + d) * NK + p) * NS + jj];
            acc += (v >= 0.f) ? v : pw * v;
        }
        // frame (k=p+128, s=jj-1): valid for jj >= 1 (jj-1 <= 255 always since jj <= 287 guarded on write)
        if (jj >= 1 && jj <= 256) {
            float v = x[(((size_t)b * ND + d) * NK + p + 128) * NS + jj - 1];
            acc += (v >= 0.f) ? v : pw * v;
        }
        t[ty + i * 8][tx] = acc;
    }
    __syncthreads();
#pragma unroll
    for (int i = 0; i < 4; i++) {
        int jl = ty + i * 8;
        int jj = j0 + jl;
        if (jj <= 256) {
            int d = d0 + tx;
            g_Af[(((size_t)b * NJ + jj) * 128 + p) * ND + d] = __float2half_rn(t[tx][jl]);
        }
    }
}

// ---------------- fused main kernel: 512 threads, 16 warps ----------------
__global__ __launch_bounds__(512, 1) void main_kernel(
    const float* __restrict__ b1g, const float* __restrict__ b2g, float* __restrict__ out)
{
    extern __shared__ char smc[];
    uint32_t sb = smem_u32(smc);
    float* s_b1 = (float*)(smc + SM_B1);
    float* s_b2 = (float*)(smc + SM_B2);
    int tid = threadIdx.x, w = tid >> 5, lane = tid & 31;
    int j = blockIdx.x, b = blockIdx.y;
    int pw = (w & 3) * 32, ow = (w >> 2) * 64;

    if (tid < 256) { s_b1[tid] = b1g[tid]; s_b2[tid] = b2g[tid]; }

    // ---- W1 -> SM_W (64KB), A -> SM_AZ (32KB) ----
    {
        const uint4* w4 = (const uint4*)g_W1f;
        for (int idx = tid; idx < 4096; idx += 512) {
            *(uint4*)(smc + SM_W + swz(idx >> 4, (idx & 15) << 4)) = w4[idx];
        }
        const uint4* a4 = (const uint4*)(g_Af + ((size_t)b * NJ + j) * (128 * ND));
        for (int idx = tid; idx < 2048; idx += 512) {
            *(uint4*)(smc + SM_AZ + swz(idx >> 4, (idx & 15) << 4)) = a4[idx];
        }
    }
    __syncthreads();

    // ldmatrix lane addressing (proven in R3)
    int ar = pw + (lane & 15);
    uint32_t acb = (uint32_t)(lane >> 4) << 4;
    int br = ow + ((lane >> 3) & 1) * 8 + (lane & 7);
    uint32_t bcb = (uint32_t)((lane >> 4) & 1) << 4;
    uint32_t uW = sb + SM_W, uA = sb + SM_AZ;

    // ---- GEMM1: D1[p=128][o=256] = A[p][d] * W1[o][d], warp tile 32x64 ----
    float acc[2][8][4];
#pragma unroll
    for (int mt = 0; mt < 2; mt++)
#pragma unroll
        for (int nt = 0; nt < 8; nt++)
#pragma unroll
            for (int q = 0; q < 4; q++) acc[mt][nt][q] = 0.f;
#pragma unroll
    for (int ks = 0; ks < 8; ks++) {
        uint32_t kb = (uint32_t)ks * 32;
        uint32_t a[2][4], bf[4][4];
#pragma unroll
        for (int mt = 0; mt < 2; mt++)
            LDSM4(a[mt][0], a[mt][1], a[mt][2], a[mt][3], uA + swz(ar + mt * 16, kb + acb));
#pragma unroll
        for (int ng = 0; ng < 4; ng++)
            LDSM4(bf[ng][0], bf[ng][1], bf[ng][2], bf[ng][3], uW + swz(br + ng * 16, kb + bcb));
#pragma unroll
        for (int mt = 0; mt < 2; mt++)
#pragma unroll
            for (int ng = 0; ng < 4; ng++) {
                mma16816(acc[mt][2 * ng],     a[mt], bf[ng][0], bf[ng][2]);
                mma16816(acc[mt][2 * ng + 1], a[mt], bf[ng][1], bf[ng][3]);
            }
    }
    __syncthreads();   // all W1/A reads complete

    // ---- epilogue1: Z = relu(D1 + nf*b1) -> fp16, channel blocks in SM_AZ ----
    float nf = (j == 0 || j == 256) ? 1.f : 2.f;
    int lr = lane >> 2, lc = (lane & 3) << 1;
    int cW = ow >> 7;
    char* zB = smc + SM_AZ + cW * 32768;
#pragma unroll
    for (int mt = 0; mt < 2; mt++) {
#pragma unroll
        for (int nt = 0; nt < 8; nt++) {
            int o = ow + nt * 8 + lc;
            int e = o & 127;
            float b0v = nf * s_b1[o], b1v = nf * s_b1[o + 1];
#pragma unroll
            for (int hf = 0; hf < 2; hf++) {
                int p = pw + mt * 16 + lr + hf * 8;
                __half2 hv;
                hv.x = __float2half_rn(fmaxf(acc[mt][nt][hf * 2]     + b0v, 0.f));
                hv.y = __float2half_rn(fmaxf(acc[mt][nt][hf * 2 + 1] + b1v, 0.f));
                *(uint32_t*)(zB + swz((uint32_t)p, (uint32_t)e << 1)) = *(uint32_t*)&hv;
            }
        }
    }
    // ---- W2 -> SM_W (W1 dead) ----
    {
        const uint4* w4 = (const uint4*)g_W2f;
        for (int idx = tid; idx < 4096; idx += 512) {
            *(uint4*)(smc + SM_W + swz(idx >> 4, (idx & 15) << 4)) = w4[idx];
        }
    }
    __syncthreads();

    // ---- GEMM2 per channel: D2[p=128][o2=256] = Z_c[p][e] * W2[o2][e] ----
    int l0 = j * 128 - 64;
#pragma unroll 1
    for (int c = 0; c < 2; c++) {
        uint32_t uZ = sb + SM_AZ + c * 32768;
#pragma unroll
        for (int mt = 0; mt < 2; mt++)
#pragma unroll
            for (int nt = 0; nt < 8; nt++)
#pragma unroll
                for (int q = 0; q < 4; q++) acc[mt][nt][q] = 0.f;
#pragma unroll
        for (int ks = 0; ks < 8; ks++) {
            uint32_t kb = (uint32_t)ks * 32;
            uint32_t a[2][4], bf[4][4];
#pragma unroll
            for (int mt = 0; mt < 2; mt++)
                LDSM4(a[mt][0], a[mt][1], a[mt][2], a[mt][3], uZ + swz(ar + mt * 16, kb + acb));
#pragma unroll
            for (int ng = 0; ng < 4; ng++)
                LDSM4(bf[ng][0], bf[ng][1], bf[ng][2], bf[ng][3], uW + swz(br + ng * 16, kb + bcb));
#pragma unroll
            for (int mt = 0; mt < 2; mt++)
#pragma unroll
                for (int ng = 0; ng < 4; ng++) {
                    mma16816(acc[mt][2 * ng],     a[mt], bf[ng][0], bf[ng][2]);
                    mma16816(acc[mt][2 * ng + 1], a[mt], bf[ng][1], bf[ng][3]);
                }
        }
        // ---- out epilogue ----
        float* ob = out + (size_t)(b * 2 + c) * NO * TOUT;
#pragma unroll
        for (int mt = 0; mt < 2; mt++) {
#pragma unroll
            for (int hf = 0; hf < 2; hf++) {
                int p = pw + mt * 16 + lr + hf * 8;
                int l = l0 + p;
                if (l >= 0 && l < TOUT) {
#pragma unroll
                    for (int nt = 0; nt < 8; nt++) {
                        int o2 = ow + nt * 8 + lc;
                        ob[(size_t)o2 * TOUT + l]       = acc[mt][nt][hf * 2]     + s_b2[o2];
                        ob[(size_t)(o2 + 1) * TOUT + l] = acc[mt][nt][hf * 2 + 1] + s_b2[o2 + 1];
                    }
                }
            }
        }
    }
}

// ---------------------------------------------------------------------------
extern "C" void kernel_launch(void* const* d_in, const int* in_sizes, int n_in,
                              void* d_out, int out_size) {
    const float* x  = (const float*)d_in[0];
    const float* pw = (const float*)d_in[1];
    const float* w1 = (const float*)d_in[2];
    const float* b1 = (const float*)d_in[3];
    const float* w2 = (const float*)d_in[4];
    const float* b2 = (const float*)d_in[5];
    float* out = (float*)d_out;

    cudaFuncSetAttribute(main_kernel, cudaFuncAttributeMaxDynamicSharedMemorySize, SM_TOT);

    prep_all<<<dim3(9, 4, NB * 128 + 1), dim3(32, 8)>>>(x, pw, w1, w2);
    main_kernel<<<dim3(NJ, NB), 512, SM_TOT>>>(b1, b2, out);
}